// round 4
// baseline (speedup 1.0000x reference)
#include <cuda_runtime.h>
#include <cuda_bf16.h>
#include <cstdint>

#define D 128
#define MAX_NODES 100000

// Scratch for the aggregated features (no cudaMalloc allowed).
__device__ float g_agg[(size_t)MAX_NODES * D];

// ---------------------------------------------------------------------------
// Kernel 1: zero the aggregation scratch (float4 grid-stride).
// ---------------------------------------------------------------------------
__global__ void zero_agg_kernel(int n4) {
    int i = blockIdx.x * blockDim.x + threadIdx.x;
    int stride = gridDim.x * blockDim.x;
    float4 z = make_float4(0.f, 0.f, 0.f, 0.f);
    float4* p = reinterpret_cast<float4*>(g_agg);
    for (; i < n4; i += stride) p[i] = z;
}

// ---------------------------------------------------------------------------
// Kernel 2: edge scatter. One warp per edge:
//   lane l loads float4 of x[src], scales by edge value, vector-RED to agg[dst].
// red.global.add.v4.f32 is sm_90+; 1 RED.128 per lane instead of 4 scalar RED.
// ---------------------------------------------------------------------------
__global__ void scatter_kernel(const float* __restrict__ x,
                               const int*   __restrict__ erow,
                               const int*   __restrict__ ecol,
                               const float* __restrict__ evals,
                               int n_edges) {
    int e = (blockIdx.x * blockDim.x + threadIdx.x) >> 5;
    if (e >= n_edges) return;
    int lane = threadIdx.x & 31;

    int dst = erow[e];   // segment id (broadcast load across warp)
    int src = ecol[e];   // gather source
    float v = evals[e];

    const float4* xr = reinterpret_cast<const float4*>(x + (size_t)src * D);
    float4 m = xr[lane];
    m.x *= v; m.y *= v; m.z *= v; m.w *= v;

    float* d = g_agg + (size_t)dst * D + lane * 4;
    asm volatile("red.global.add.v4.f32 [%0], {%1, %2, %3, %4};"
                 :: "l"(d), "f"(m.x), "f"(m.y), "f"(m.z), "f"(m.w)
                 : "memory");
}

// ---------------------------------------------------------------------------
// Kernel 3: C[n,128] = agg[n,128] @ W[128,128], fp32.
// 256 threads/block, 128x128 tile, 8x8 register microtile per thread.
// W (64KB) + A tile (64KB) staged in 128KB dynamic smem.
// ---------------------------------------------------------------------------
__global__ void gemm_kernel(const float* __restrict__ W,
                            float* __restrict__ C, int n) {
    extern __shared__ float sm[];
    float* Ws = sm;              // [128][128]
    float* As = sm + 128 * 128;  // [128][128]

    int tid  = threadIdx.x;
    int row0 = blockIdx.x * 128;

    // Load W: [k][n] row-major -> exactly Ws layout. 128*128 floats = 4096 float4.
    {
        const float4* Wg = reinterpret_cast<const float4*>(W);
        float4* Wsh = reinterpret_cast<float4*>(Ws);
        #pragma unroll
        for (int i = 0; i < 16; i++)
            Wsh[tid + i * 256] = Wg[tid + i * 256];
    }
    // Load A tile (guard tail rows with zeros).
    {
        float4* Ash = reinterpret_cast<float4*>(As);
        #pragma unroll
        for (int i = 0; i < 16; i++) {
            int idx = tid + i * 256;      // [0, 4096)
            int r = idx >> 5;             // row in tile (32 float4 per row)
            float4 val = make_float4(0.f, 0.f, 0.f, 0.f);
            if (row0 + r < n)
                val = reinterpret_cast<const float4*>(
                          g_agg + (size_t)(row0 + r) * D)[idx & 31];
            Ash[idx] = val;
        }
    }
    __syncthreads();

    int cg = tid & 15;   // column group: 8 cols starting at cg*8
    int rg = tid >> 4;   // row group:    8 rows starting at rg*8

    float acc[8][8];
    #pragma unroll
    for (int i = 0; i < 8; i++)
        #pragma unroll
        for (int j = 0; j < 8; j++) acc[i][j] = 0.f;

    #pragma unroll 4
    for (int k = 0; k < 128; k++) {
        float a[8];
        #pragma unroll
        for (int i = 0; i < 8; i++)
            a[i] = As[(rg * 8 + i) * 128 + k];
        const float4* wrow = reinterpret_cast<const float4*>(Ws + k * 128 + cg * 8);
        float4 b0 = wrow[0];
        float4 b1 = wrow[1];
        float b[8] = {b0.x, b0.y, b0.z, b0.w, b1.x, b1.y, b1.z, b1.w};
        #pragma unroll
        for (int i = 0; i < 8; i++)
            #pragma unroll
            for (int j = 0; j < 8; j++)
                acc[i][j] = fmaf(a[i], b[j], acc[i][j]);
    }

    // Store 8x8 microtile (two float4 per row).
    #pragma unroll
    for (int i = 0; i < 8; i++) {
        int r = row0 + rg * 8 + i;
        if (r < n) {
            float4* out = reinterpret_cast<float4*>(C + (size_t)r * D + cg * 8);
            out[0] = make_float4(acc[i][0], acc[i][1], acc[i][2], acc[i][3]);
            out[1] = make_float4(acc[i][4], acc[i][5], acc[i][6], acc[i][7]);
        }
    }
}

// ---------------------------------------------------------------------------
// Launch
// ---------------------------------------------------------------------------
extern "C" void kernel_launch(void* const* d_in, const int* in_sizes, int n_in,
                              void* d_out, int out_size) {
    const float* x     = (const float*)d_in[0];
    const int*   erow  = (const int*)  d_in[1];
    const int*   ecol  = (const int*)  d_in[2];
    const float* evals = (const float*)d_in[3];
    const float* W     = (const float*)d_in[4];
    float*       out   = (float*)d_out;

    int n_nodes = in_sizes[0] / D;   // 100000
    int n_edges = in_sizes[1];       // 1600000

    // 1) zero agg scratch
    {
        int n4 = n_nodes * (D / 4);
        int threads = 256;
        int blocks = (n4 + threads * 4 - 1) / (threads * 4);
        if (blocks > 8192) blocks = 8192;
        zero_agg_kernel<<<blocks, threads>>>(n4);
    }
    // 2) edge scatter (1 warp per edge)
    {
        int threads = 256;
        int warps_per_block = threads / 32;
        int blocks = (n_edges + warps_per_block - 1) / warps_per_block;
        scatter_kernel<<<blocks, threads>>>(x, erow, ecol, evals, n_edges);
    }
    // 3) dense GEMM agg @ W -> out
    {
        int smem = 2 * 128 * 128 * sizeof(float);  // 128 KB
        cudaFuncSetAttribute(gemm_kernel,
                             cudaFuncAttributeMaxDynamicSharedMemorySize, smem);
        int blocks = (n_nodes + 127) / 128;
        gemm_kernel<<<blocks, 256, smem>>>(W, out, n_nodes);
    }
}